// round 14
// baseline (speedup 1.0000x reference)
#include <cuda_runtime.h>
#include <cuda_bf16.h>

#define HH 1024
#define WW 1024
#define NB 8
#define PLANE (HH * WW)

// Load the 4-wide window (cols w0-1 .. w0+2) of row hh, zero-padded outside.
// One aligned LDG.64 + two predicated edge scalars; all three independent
// (preserve MLP — no shuffles / no smem staging / no path specialization,
// per R2/R8/R11). int offsets only.
__device__ __forceinline__ void load_row4(const float* __restrict__ base, int hh,
                                          int w0, float v[4]) {
    if (hh < 0 || hh >= HH) {
        v[0] = v[1] = v[2] = v[3] = 0.0f;
        return;
    }
    const float* row = base + hh * WW;
    float2 m = *reinterpret_cast<const float2*>(row + w0);
    v[1] = m.x; v[2] = m.y;
    v[0] = (w0 > 0) ? row[w0 - 1] : 0.0f;
    v[3] = (w0 + 2 < WW) ? row[w0 + 2] : 0.0f;
}

// Fire-and-forget L1 prefetch: no destination register, no scoreboard.
__device__ __forceinline__ void pf_l1(const float* p) {
    asm volatile("prefetch.global.L1 [%0];" :: "l"(p));
}

__global__ void __launch_bounds__(128, 7)
small_sm_block_kernel(const float* __restrict__ image,
                      const float* __restrict__ x,
                      const float* __restrict__ wgt,   // (9,1,3,3) = 81
                      const float* __restrict__ bias,  // (9,)
                      float* __restrict__ y) {
    __shared__ float sw[81];
    __shared__ float sb[9];
    const int t = threadIdx.x;
    if (t < 81) sw[t] = wgt[t];
    if (t < 9)  sb[t] = bias[t];
    __syncthreads();

    const int h0 = blockIdx.y * 2;                  // output rows h0, h0+1
    const int w0 = (blockIdx.x * 128 + t) * 2;      // output cols w0, w0+1
    const int orow = h0 * WW + w0;

    // Row validity (block-uniform; only y-edge blocks ever see false).
    const bool rv0 = (h0 - 1) >= 0;
    const bool rv3 = (h0 + 2) < HH;

    // ---- image window: 4 rows (h0-1..h0+2) x 4 cols ----
    float img[4][4];
#pragma unroll
    for (int r = 0; r < 4; r++) load_row4(image, h0 - 1 + r, w0, img[r]);

    // Warm L1 for batches 0 and 1 while K is being built.
    {
        const int roff = (h0 - 1) * WW + w0;
#pragma unroll
        for (int r = 0; r < 4; r++) {
            if ((r > 0 && r < 3) || (r == 0 && rv0) || (r == 3 && rv3)) {
                pf_l1(x + roff + r * WW);
                pf_l1(x + PLANE + roff + r * WW);
            }
        }
    }

    // ---- per-pixel kernels: KA = K @ row h0, KB = K @ row h0+1 ----
    float KA[9][2], KB[9][2];
#pragma unroll
    for (int j = 0; j < 9; j++) {
        const float bj = sb[j];
        KA[j][0] = bj; KA[j][1] = bj;
        KB[j][0] = bj; KB[j][1] = bj;
#pragma unroll
        for (int a = 0; a < 3; a++) {
#pragma unroll
            for (int d = 0; d < 3; d++) {
                const float wv = sw[j * 9 + a * 3 + d];
                KA[j][0] += img[a][d]         * wv;
                KA[j][1] += img[a][d + 1]     * wv;
                KB[j][0] += img[a + 1][d]     * wv;
                KB[j][1] += img[a + 1][d + 1] * wv;
            }
        }
    }

    // ---- apply: 4 x-rows serve 2 output rows; distance-2 L1 prefetch ----
#pragma unroll 2
    for (int b = 0; b < NB; b++) {
        // prefetch batch b+2 into L1 (fire-and-forget, covers ~2 iterations)
        if (b + 2 < NB) {
            const int poff = (b + 2) * PLANE + (h0 - 1) * WW + w0;
#pragma unroll
            for (int r = 0; r < 4; r++) {
                if ((r > 0 && r < 3) || (r == 0 && rv0) || (r == 3 && rv3))
                    pf_l1(x + poff + r * WW);
            }
        }

        const float* xb = x + b * PLANE;
        float xr[4][4];
#pragma unroll
        for (int r = 0; r < 4; r++) load_row4(xb, h0 - 1 + r, w0, xr[r]);

        float a0 = 0.f, a1 = 0.f, b0 = 0.f, b1 = 0.f;
#pragma unroll
        for (int a = 0; a < 3; a++) {
#pragma unroll
            for (int d = 0; d < 3; d++) {
                const int j = a * 3 + d;
                a0 += xr[a][d]         * KA[j][0];
                a1 += xr[a][d + 1]     * KA[j][1];
                b0 += xr[a + 1][d]     * KB[j][0];
                b1 += xr[a + 1][d + 1] * KB[j][1];
            }
        }

        float* yb = y + b * PLANE + orow;
        float2 oA; oA.x = a0; oA.y = a1;
        float2 oB; oB.x = b0; oB.y = b1;
        *reinterpret_cast<float2*>(yb)      = oA;   // row h0
        *reinterpret_cast<float2*>(yb + WW) = oB;   // row h0+1
    }
}

extern "C" void kernel_launch(void* const* d_in, const int* in_sizes, int n_in,
                              void* d_out, int out_size) {
    const float* image = (const float*)d_in[0];  // (1, 1024, 1024)
    const float* x     = (const float*)d_in[1];  // (8, 1, 1024, 1024)
    const float* klw   = (const float*)d_in[2];  // (9, 1, 3, 3)
    const float* klb   = (const float*)d_in[3];  // (9,)
    float* y = (float*)d_out;                    // (8, 1, 1024, 1024)

    dim3 block(128);
    dim3 grid(WW / 2 / 128, HH / 2);  // (4, 512) = 2048 blocks
    small_sm_block_kernel<<<grid, block>>>(image, x, klw, klb, y);
}

// round 15
// speedup vs baseline: 1.1064x; 1.1064x over previous
#include <cuda_runtime.h>
#include <cuda_bf16.h>

#define HH 1024
#define WW 1024
#define NB 8
#define PLANE (HH * WW)

// Load the 4-wide window (cols w0-1 .. w0+2) of row hh, zero-padded outside.
// One aligned LDG.64 + two predicated edge scalars; all three independent
// (preserve MLP — no shuffles / no smem staging / no path specialization /
// no software prefetch, per R2/R8/R11/R14). int offsets only.
__device__ __forceinline__ void load_row4(const float* __restrict__ base, int hh,
                                          int w0, float v[4]) {
    if (hh < 0 || hh >= HH) {
        v[0] = v[1] = v[2] = v[3] = 0.0f;
        return;
    }
    const float* row = base + hh * WW;
    float2 m = *reinterpret_cast<const float2*>(row + w0);
    v[1] = m.x; v[2] = m.y;
    v[0] = (w0 > 0) ? row[w0 - 1] : 0.0f;
    v[3] = (w0 + 2 < WW) ? row[w0 + 2] : 0.0f;
}

__global__ void __launch_bounds__(128, 7)
small_sm_block_kernel(const float* __restrict__ image,
                      const float* __restrict__ x,
                      const float* __restrict__ wgt,   // (9,1,3,3) = 81
                      const float* __restrict__ bias,  // (9,)
                      float* __restrict__ y) {
    __shared__ float sw[81];
    __shared__ float sb[9];
    const int t = threadIdx.x;
    if (t < 81) sw[t] = wgt[t];
    if (t < 9)  sb[t] = bias[t];
    __syncthreads();

    const int h0 = blockIdx.y * 2;                  // output rows h0, h0+1
    const int w0 = (blockIdx.x * 128 + t) * 2;      // output cols w0, w0+1
    const int orow = h0 * WW + w0;

    // ---- image window: 4 rows (h0-1..h0+2) x 4 cols ----
    float img[4][4];
#pragma unroll
    for (int r = 0; r < 4; r++) load_row4(image, h0 - 1 + r, w0, img[r]);

    // ---- per-pixel kernels: KA = K @ row h0 (img rows 0-2),
    //      KB = K @ row h0+1 (img rows 1-3); 2 cols each ----
    float KA[9][2], KB[9][2];
#pragma unroll
    for (int j = 0; j < 9; j++) {
        const float bj = sb[j];
        KA[j][0] = bj; KA[j][1] = bj;
        KB[j][0] = bj; KB[j][1] = bj;
#pragma unroll
        for (int a = 0; a < 3; a++) {
#pragma unroll
            for (int d = 0; d < 3; d++) {
                const float wv = sw[j * 9 + a * 3 + d];
                KA[j][0] += img[a][d]         * wv;
                KA[j][1] += img[a][d + 1]     * wv;
                KB[j][0] += img[a + 1][d]     * wv;
                KB[j][1] += img[a + 1][d + 1] * wv;
            }
        }
    }

    // ---- apply: 4 x-rows serve 2 output rows, 2 cols each.
    //      FULL unroll: per-iteration register renaming lets ptxas hoist
    //      batch b+1's 12 independent loads into batch b's FMA shadow with
    //      no architectural copies (the fix for R12's failed manual pipeline). ----
#pragma unroll
    for (int b = 0; b < NB; b++) {
        const float* xb = x + b * PLANE;
        float xr[4][4];
#pragma unroll
        for (int r = 0; r < 4; r++) load_row4(xb, h0 - 1 + r, w0, xr[r]);

        float a0 = 0.f, a1 = 0.f, b0 = 0.f, b1 = 0.f;
#pragma unroll
        for (int a = 0; a < 3; a++) {
#pragma unroll
            for (int d = 0; d < 3; d++) {
                const int j = a * 3 + d;
                a0 += xr[a][d]         * KA[j][0];
                a1 += xr[a][d + 1]     * KA[j][1];
                b0 += xr[a + 1][d]     * KB[j][0];
                b1 += xr[a + 1][d + 1] * KB[j][1];
            }
        }

        float* yb = y + b * PLANE + orow;
        float2 oA; oA.x = a0; oA.y = a1;
        float2 oB; oB.x = b0; oB.y = b1;
        *reinterpret_cast<float2*>(yb)      = oA;   // row h0
        *reinterpret_cast<float2*>(yb + WW) = oB;   // row h0+1
    }
}

extern "C" void kernel_launch(void* const* d_in, const int* in_sizes, int n_in,
                              void* d_out, int out_size) {
    const float* image = (const float*)d_in[0];  // (1, 1024, 1024)
    const float* x     = (const float*)d_in[1];  // (8, 1, 1024, 1024)
    const float* klw   = (const float*)d_in[2];  // (9, 1, 3, 3)
    const float* klb   = (const float*)d_in[3];  // (9,)
    float* y = (float*)d_out;                    // (8, 1, 1024, 1024)

    dim3 block(128);
    dim3 grid(WW / 2 / 128, HH / 2);  // (4, 512) = 2048 blocks
    small_sm_block_kernel<<<grid, block>>>(image, x, klw, klb, y);
}

// round 16
// speedup vs baseline: 1.1083x; 1.0017x over previous
#include <cuda_runtime.h>
#include <cuda_bf16.h>

#define HH 1024
#define WW 1024
#define NB 8
#define PLANE (HH * WW)

// Load the 4-wide window (cols -1..+2 around p) of one row. One aligned
// LDG.64 + two predicated edge scalars; all three independent (preserve MLP —
// no shuffles / smem / prefetch / packing, per R2/R5/R8/R14). Addresses are
// [p + small-immediate] so no per-load ALU.
__device__ __forceinline__ void load_win4(const float* __restrict__ p,
                                          bool lft, bool rgt, float v[4]) {
    float2 m = *reinterpret_cast<const float2*>(p);
    v[1] = m.x; v[2] = m.y;
    v[0] = lft ? p[-1] : 0.0f;
    v[3] = rgt ? p[2]  : 0.0f;
}

__global__ void __launch_bounds__(128, 7)
small_sm_block_kernel(const float* __restrict__ image,
                      const float* __restrict__ x,
                      const float* __restrict__ wgt,   // (9,1,3,3) = 81
                      const float* __restrict__ bias,  // (9,)
                      float* __restrict__ y) {
    __shared__ float sw[81];
    __shared__ float sb[9];
    const int t = threadIdx.x;
    if (t < 81) sw[t] = wgt[t];
    if (t < 9)  sb[t] = bias[t];
    __syncthreads();

    const int h0 = blockIdx.y * 2;                  // output rows h0, h0+1
    const int w0 = (blockIdx.x * 128 + t) * 2;      // output cols w0, w0+1

    // Hoisted bounds (block-uniform rows; thread-constant cols).
    const bool top = h0 > 0;            // row h0-1 valid
    const bool bot = h0 + 2 < HH;       // row h0+2 valid
    const bool lft = w0 > 0;
    const bool rgt = w0 + 2 < WW;

    // ---- image window: 4 rows (h0-1..h0+2) x 4 cols ----
    const float* ip = image + (h0 - 1) * WW + w0;   // row h0-1 base (guarded)
    float img[4][4];
    if (top) load_win4(ip, lft, rgt, img[0]);
    else     { img[0][0] = img[0][1] = img[0][2] = img[0][3] = 0.f; }
    load_win4(ip + WW,     lft, rgt, img[1]);
    load_win4(ip + 2 * WW, lft, rgt, img[2]);
    if (bot) load_win4(ip + 3 * WW, lft, rgt, img[3]);
    else     { img[3][0] = img[3][1] = img[3][2] = img[3][3] = 0.f; }

    // ---- per-pixel kernels: KA = K @ row h0 (img rows 0-2),
    //      KB = K @ row h0+1 (img rows 1-3); 2 cols each ----
    float KA[9][2], KB[9][2];
#pragma unroll
    for (int j = 0; j < 9; j++) {
        const float bj = sb[j];
        KA[j][0] = bj; KA[j][1] = bj;
        KB[j][0] = bj; KB[j][1] = bj;
#pragma unroll
        for (int a = 0; a < 3; a++) {
#pragma unroll
            for (int d = 0; d < 3; d++) {
                const float wv = sw[j * 9 + a * 3 + d];
                KA[j][0] += img[a][d]         * wv;
                KA[j][1] += img[a][d + 1]     * wv;
                KB[j][0] += img[a + 1][d]     * wv;
                KB[j][1] += img[a + 1][d + 1] * wv;
            }
        }
    }

    // ---- apply: full unroll + pointer-bump addressing.
    //      xp/yp advance by PLANE once per batch (2 IADD each); every load and
    //      store is [ptr + imm] (row offsets <= 48KB fit the 24-bit field). ----
    const float* xp = x + (h0 - 1) * WW + w0;
    float*       yp = y + h0 * WW + w0;
#pragma unroll
    for (int b = 0; b < NB; b++) {
        float xr[4][4];
        if (top) load_win4(xp, lft, rgt, xr[0]);
        else     { xr[0][0] = xr[0][1] = xr[0][2] = xr[0][3] = 0.f; }
        load_win4(xp + WW,     lft, rgt, xr[1]);
        load_win4(xp + 2 * WW, lft, rgt, xr[2]);
        if (bot) load_win4(xp + 3 * WW, lft, rgt, xr[3]);
        else     { xr[3][0] = xr[3][1] = xr[3][2] = xr[3][3] = 0.f; }

        float a0 = 0.f, a1 = 0.f, b0 = 0.f, b1 = 0.f;
#pragma unroll
        for (int a = 0; a < 3; a++) {
#pragma unroll
            for (int d = 0; d < 3; d++) {
                const int j = a * 3 + d;
                a0 += xr[a][d]         * KA[j][0];
                a1 += xr[a][d + 1]     * KA[j][1];
                b0 += xr[a + 1][d]     * KB[j][0];
                b1 += xr[a + 1][d + 1] * KB[j][1];
            }
        }

        float2 oA; oA.x = a0; oA.y = a1;
        float2 oB; oB.x = b0; oB.y = b1;
        *reinterpret_cast<float2*>(yp)      = oA;   // row h0
        *reinterpret_cast<float2*>(yp + WW) = oB;   // row h0+1

        xp += PLANE;
        yp += PLANE;
    }
}

extern "C" void kernel_launch(void* const* d_in, const int* in_sizes, int n_in,
                              void* d_out, int out_size) {
    const float* image = (const float*)d_in[0];  // (1, 1024, 1024)
    const float* x     = (const float*)d_in[1];  // (8, 1, 1024, 1024)
    const float* klw   = (const float*)d_in[2];  // (9, 1, 3, 3)
    const float* klb   = (const float*)d_in[3];  // (9,)
    float* y = (float*)d_out;                    // (8, 1, 1024, 1024)

    dim3 block(128);
    dim3 grid(WW / 2 / 128, HH / 2);  // (4, 512) = 2048 blocks
    small_sm_block_kernel<<<grid, block>>>(image, x, klw, klb, y);
}